// round 6
// baseline (speedup 1.0000x reference)
#include <cuda_runtime.h>
#include <cuda_bf16.h>
#include <cstdint>
#include <math.h>

#define NROWS 8192
#define D     128
#define INV_T (1.0f / 0.07f)

#define NT       64
#define NTILES   2080          // NT*(NT+1)/2
#define STAGES   4
#define CHUNKS   12            // p0: a*a (4), p1: a*b (4), p2: b*a (4), each k32
#define ROWPITCH 48            // bytes per smem row (32 data + 16 pad, LDSM conflict-free)
#define TILEB    (128 * ROWPITCH)          // 6144
#define STAGEB   (2 * TILEB)               // 12288
#define SMEM_DYN_BYTES (STAGES * STAGEB)   // 49152

// ---------------- device scratch -------------------------------------------
__device__ char  g_a8[NROWS * 256];   // [row][0:128]=a (scale 2^-7), [128:256]=b (scale 2^-22)
__device__ float g_pos[NROWS];
__device__ float g_neg[NROWS];
__device__ int   g_lab[NROWS];

// ---------------- helpers ---------------------------------------------------
__device__ __forceinline__ uint32_t smem_u32(const void* p) {
    return (uint32_t)__cvta_generic_to_shared(p);
}
__device__ __forceinline__ void cpasync16(uint32_t s, const void* g) {
    asm volatile("cp.async.cg.shared.global [%0], [%1], 16;" :: "r"(s), "l"(g));
}
__device__ __forceinline__ void cp_commit() {
    asm volatile("cp.async.commit_group;" ::: "memory");
}
template <int N>
__device__ __forceinline__ void cp_wait() {
    asm volatile("cp.async.wait_group %0;" :: "n"(N) : "memory");
}
__device__ __forceinline__ void ldmx4(uint32_t* r, uint32_t addr) {
    asm volatile("ldmatrix.sync.aligned.m8n8.x4.shared.b16 {%0,%1,%2,%3}, [%4];"
                 : "=r"(r[0]), "=r"(r[1]), "=r"(r[2]), "=r"(r[3]) : "r"(addr));
}
__device__ __forceinline__ void mma_s8(int* c, const uint32_t* a, uint32_t b0, uint32_t b1) {
    asm volatile(
        "mma.sync.aligned.m16n8k32.row.col.s32.s8.s8.s32 "
        "{%0,%1,%2,%3}, {%4,%5,%6,%7}, {%8,%9}, {%0,%1,%2,%3};"
        : "+r"(c[0]), "+r"(c[1]), "+r"(c[2]), "+r"(c[3])
        : "r"(a[0]), "r"(a[1]), "r"(a[2]), "r"(a[3]), "r"(b0), "r"(b1));
}
__device__ __forceinline__ int clamp_i(float v, int lim) {
    int x = __float2int_rn(v);
    return max(-lim, min(lim, x));
}

// ---------------------------------------------------------------------------
// Kernel 1: warp-per-row normalize -> int8 a/b split; labels; zero accums.
// ---------------------------------------------------------------------------
__global__ void __launch_bounds__(256) normalize_kernel(
    const float* __restrict__ feat,
    const int*   __restrict__ lab32)
{
    const int warp = threadIdx.x >> 5;
    const int lane = threadIdx.x & 31;
    const int row  = blockIdx.x * 8 + warp;

    float4 v = *(const float4*)&feat[row * D + lane * 4];
    float ss = v.x * v.x + v.y * v.y + v.z * v.z + v.w * v.w;
    #pragma unroll
    for (int o = 16; o > 0; o >>= 1) ss += __shfl_xor_sync(0xffffffffu, ss, o);
    float inv = 1.0f / fmaxf(sqrtf(ss), 1e-8f);

    float f[4] = { v.x * inv, v.y * inv, v.z * inv, v.w * inv };
    uint32_t pa = 0, pb = 0;
    #pragma unroll
    for (int k = 0; k < 4; k++) {
        int a = clamp_i(f[k] * 128.0f, 127);
        float r = f[k] - (float)a * (1.0f / 128.0f);
        int b = clamp_i(r * 4194304.0f * (1.0f / 128.0f) * 1024.0f, 127); // r * 2^15
        pa |= (uint32_t)(unsigned char)(char)a << (k * 8);
        pb |= (uint32_t)(unsigned char)(char)b << (k * 8);
    }
    *(uint32_t*)&g_a8[row * 256 + lane * 4]       = pa;
    *(uint32_t*)&g_a8[row * 256 + 128 + lane * 4] = pb;

    if (lane == 0) {
        g_pos[row] = 0.0f;
        g_neg[row] = 0.0f;
        bool is64 = true;
        #pragma unroll 8
        for (int i = 0; i < 32; i++)
            if (lab32[2 * i + 1] != 0) { is64 = false; break; }
        g_lab[row] = is64 ? lab32[2 * row] : lab32[row];
    }
}

// ---------------------------------------------------------------------------
// Kernel 2: upper-triangular 128x128 int8 mma.sync tiles.
//   phase 1 (chunks 0-3):  I1 = a.a'   -> facc = I1 * 2^-14 (exact int32)
//   phase 2 (chunks 4-11): I2 = a.b' + b.a'  -> v = facc + I2 * 2^-22
// Fused clip/exp/mask epilogue feeds row sums AND (off-diag) column sums.
// ---------------------------------------------------------------------------
__device__ __forceinline__ void load_chunk(uint32_t stageBase, int chunk,
                                           int aRowBase, int bRowBase, int tid)
{
    const int p  = chunk >> 2;
    const int cc = chunk & 3;
    const int aCol = ((p == 2) ? 128 : 0) + cc * 32;
    const int bCol = ((p == 1) ? 128 : 0) + cc * 32;
    const int r = tid >> 1;
    const int h = tid & 1;
    uint32_t s = stageBase + r * ROWPITCH + h * 16;
    cpasync16(s,         &g_a8[(aRowBase + r) * 256 + aCol + h * 16]);
    cpasync16(s + TILEB, &g_a8[(bRowBase + r) * 256 + bCol + h * 16]);
}

__global__ void __launch_bounds__(256, 1) sim_mma_kernel()
{
    extern __shared__ char dsm[];
    __shared__ int labA[128];
    __shared__ int labB[128];

    const uint32_t smBase = smem_u32(dsm);
    const int tid  = threadIdx.x;
    const int warp = tid >> 5;
    const int lane = tid & 31;
    const int warpRow = warp >> 1;
    const int warpCol = warp & 1;

    // decode linear tile id -> upper-triangular (i, j), i <= j
    int ti = blockIdx.x;
    int i  = (int)floorf((129.0f - sqrtf(129.0f * 129.0f - 8.0f * (float)ti)) * 0.5f);
    while (i > 0 && ti < i * NT - i * (i - 1) / 2) --i;
    while (ti >= (i + 1) * NT - (i + 1) * i / 2) ++i;
    const int j = i + (ti - (i * NT - i * (i - 1) / 2));
    const bool diag = (i == j);
    const int aRowBase = i * 128;
    const int bRowBase = j * 128;

    if (tid < 128) {
        labA[tid] = g_lab[aRowBase + tid];
        labB[tid] = g_lab[bRowBase + tid];
    }

    #pragma unroll
    for (int s = 0; s < STAGES - 1; s++) {
        load_chunk(smBase + s * STAGEB, s, aRowBase, bRowBase, tid);
        cp_commit();
    }

    int   iacc[2][8][4];
    float facc[2][8][4];
    #pragma unroll
    for (int a = 0; a < 2; a++)
        #pragma unroll
        for (int b = 0; b < 8; b++)
            #pragma unroll
            for (int k = 0; k < 4; k++) { iacc[a][b][k] = 0; facc[a][b][k] = 0.0f; }

    uint32_t aOff[2];
    #pragma unroll
    for (int mi = 0; mi < 2; mi++)
        aOff[mi] = (uint32_t)((warpRow * 32 + mi * 16 + (lane & 15)) * ROWPITCH
                              + ((lane >> 4) * 16));
    uint32_t bOff[4];
    #pragma unroll
    for (int nt = 0; nt < 4; nt++)
        bOff[nt] = (uint32_t)((warpCol * 64 + nt * 16 + (lane & 7) + ((lane & 16) ? 8 : 0))
                              * ROWPITCH + ((lane & 8) ? 16 : 0));

    #pragma unroll 1
    for (int c = 0; c < CHUNKS; c++) {
        cp_wait<STAGES - 2>();
        __syncthreads();

        int nf = c + STAGES - 1;
        if (nf < CHUNKS)
            load_chunk(smBase + (nf % STAGES) * STAGEB, nf, aRowBase, bRowBase, tid);
        cp_commit();

        const uint32_t aS = smBase + (c % STAGES) * STAGEB;
        const uint32_t bS = aS + TILEB;

        uint32_t a[2][4];
        ldmx4(a[0], aS + aOff[0]);
        ldmx4(a[1], aS + aOff[1]);
        uint32_t b[4][4];
        #pragma unroll
        for (int nt = 0; nt < 4; nt++)
            ldmx4(b[nt], bS + bOff[nt]);
        #pragma unroll
        for (int mi = 0; mi < 2; mi++)
            #pragma unroll
            for (int n8 = 0; n8 < 8; n8++) {
                const uint32_t* bf = b[n8 >> 1];
                if (n8 & 1) mma_s8(iacc[mi][n8], a[mi], bf[2], bf[3]);
                else        mma_s8(iacc[mi][n8], a[mi], bf[0], bf[1]);
            }

        if (c == 3) {
            // phase 1 done: fold exact I1 into float at scale 2^-14, reset int acc
            #pragma unroll
            for (int mi = 0; mi < 2; mi++)
                #pragma unroll
                for (int n8 = 0; n8 < 8; n8++)
                    #pragma unroll
                    for (int k = 0; k < 4; k++) {
                        facc[mi][n8][k] = (float)iacc[mi][n8][k] * (1.0f / 16384.0f);
                        iacc[mi][n8][k] = 0;
                    }
        }
    }

    // ---------------- fused epilogue (row + column sums) ----------------
    const int g   = lane >> 2;
    const int tig = lane & 3;

    float colPos[16], colNeg[16];
    #pragma unroll
    for (int x = 0; x < 16; x++) { colPos[x] = 0.0f; colNeg[x] = 0.0f; }

    #pragma unroll
    for (int mi = 0; mi < 2; mi++) {
        #pragma unroll
        for (int h = 0; h < 2; h++) {
            const int rT   = warpRow * 32 + mi * 16 + h * 8 + g;
            const int lrow = labA[rT];
            float rowPos = 0.0f, rowNeg = 0.0f;
            #pragma unroll
            for (int n8 = 0; n8 < 8; n8++) {
                #pragma unroll
                for (int e = 0; e < 2; e++) {
                    const int cT = warpCol * 64 + n8 * 8 + 2 * tig + e;
                    float v = facc[mi][n8][h * 2 + e]
                            + (float)iacc[mi][n8][h * 2 + e] * (1.0f / 4194304.0f);
                    float s = fminf(fmaxf(v * INV_T, -10.0f), 10.0f);
                    float ex = __expf(s);
                    if (diag) ex = (rT == cT) ? 0.0f : ex;
                    bool m = (lrow == labB[cT]);
                    rowNeg += ex;
                    rowPos += m ? ex : 0.0f;
                    if (!diag) {
                        colNeg[n8 * 2 + e] += ex;
                        colPos[n8 * 2 + e] += m ? ex : 0.0f;
                    }
                }
            }
            #pragma unroll
            for (int o = 1; o < 4; o <<= 1) {
                rowPos += __shfl_xor_sync(0xffffffffu, rowPos, o);
                rowNeg += __shfl_xor_sync(0xffffffffu, rowNeg, o);
            }
            if (tig == 0) {
                atomicAdd(&g_pos[aRowBase + rT], rowPos);
                atomicAdd(&g_neg[aRowBase + rT], rowNeg);
            }
        }
    }

    if (!diag) {
        #pragma unroll
        for (int x = 0; x < 16; x++) {
            #pragma unroll
            for (int o = 4; o < 32; o <<= 1) {
                colPos[x] += __shfl_xor_sync(0xffffffffu, colPos[x], o);
                colNeg[x] += __shfl_xor_sync(0xffffffffu, colNeg[x], o);
            }
        }
        if (g == 0) {
            #pragma unroll
            for (int x = 0; x < 16; x++) {
                const int cT = warpCol * 64 + (x >> 1) * 8 + 2 * tig + (x & 1);
                atomicAdd(&g_pos[bRowBase + cT], colPos[x]);
                atomicAdd(&g_neg[bRowBase + cT], colNeg[x]);
            }
        }
    }
}

// ---------------------------------------------------------------------------
// Kernel 3: final loss reduction.
// ---------------------------------------------------------------------------
__global__ void __launch_bounds__(256) loss_kernel(float* __restrict__ out)
{
    int t = threadIdx.x;
    float s = 0.0f;
    for (int idx = t; idx < NROWS; idx += 256) {
        float p = fmaxf(g_pos[idx], 1e-8f);
        float n = fmaxf(g_neg[idx], 1e-8f);
        s += logf(n) - logf(p);
    }
    __shared__ float red[256];
    red[t] = s;
    __syncthreads();
    #pragma unroll
    for (int o = 128; o > 0; o >>= 1) {
        if (t < o) red[t] += red[t + o];
        __syncthreads();
    }
    if (t == 0) out[0] = red[0] * (1.0f / (float)NROWS);
}

// ---------------------------------------------------------------------------
extern "C" void kernel_launch(void* const* d_in, const int* in_sizes, int n_in,
                              void* d_out, int out_size)
{
    const float* feat  = (const float*)d_in[0];
    const int*   lab32 = (const int*)d_in[1];
    float*       out   = (float*)d_out;

    static bool attr_set = false;
    if (!attr_set) {
        cudaFuncSetAttribute(sim_mma_kernel, cudaFuncAttributeMaxDynamicSharedMemorySize,
                             SMEM_DYN_BYTES);
        attr_set = true;
    }

    normalize_kernel<<<NROWS / 8, 256>>>(feat, lab32);
    sim_mma_kernel<<<NTILES, 256, SMEM_DYN_BYTES>>>();
    loss_kernel<<<1, 256>>>(out);
}

// round 7
// speedup vs baseline: 3.7364x; 3.7364x over previous
#include <cuda_runtime.h>
#include <cuda_bf16.h>
#include <cstdint>
#include <math.h>

#define NROWS 8192
#define D     128
#define INV_T (1.0f / 0.07f)

#define NT       64
#define NTILES   2080          // NT*(NT+1)/2
#define STAGES   4
#define CHUNKS   4             // single bf16 product, 4 x k32 chunks
#define ROWPITCH 80            // 64B data + 16B pad (LDSM conflict-free)
#define TILEB    (128 * ROWPITCH)          // 10240
#define STAGEB   (2 * TILEB)               // 20480
#define SMEM_DYN_BYTES (STAGES * STAGEB)   // 81920

// ---------------- device scratch -------------------------------------------
__device__ __nv_bfloat16 g_f16[NROWS * D];   // normalized features, bf16
__device__ float g_pos[NROWS];
__device__ float g_neg[NROWS];
__device__ int   g_lab[NROWS];

// ---------------- helpers ---------------------------------------------------
__device__ __forceinline__ uint32_t smem_u32(const void* p) {
    return (uint32_t)__cvta_generic_to_shared(p);
}
__device__ __forceinline__ void cpasync16(uint32_t s, const void* g) {
    asm volatile("cp.async.cg.shared.global [%0], [%1], 16;" :: "r"(s), "l"(g));
}
__device__ __forceinline__ void cp_commit() {
    asm volatile("cp.async.commit_group;" ::: "memory");
}
template <int N>
__device__ __forceinline__ void cp_wait() {
    asm volatile("cp.async.wait_group %0;" :: "n"(N) : "memory");
}
__device__ __forceinline__ void ldmx4(uint32_t* r, uint32_t addr) {
    asm volatile("ldmatrix.sync.aligned.m8n8.x4.shared.b16 {%0,%1,%2,%3}, [%4];"
                 : "=r"(r[0]), "=r"(r[1]), "=r"(r[2]), "=r"(r[3]) : "r"(addr));
}
__device__ __forceinline__ void mma16816(float* c, const uint32_t* a, uint32_t b0, uint32_t b1) {
    asm volatile(
        "mma.sync.aligned.m16n8k16.row.col.f32.bf16.bf16.f32 "
        "{%0,%1,%2,%3}, {%4,%5,%6,%7}, {%8,%9}, {%0,%1,%2,%3};"
        : "+f"(c[0]), "+f"(c[1]), "+f"(c[2]), "+f"(c[3])
        : "r"(a[0]), "r"(a[1]), "r"(a[2]), "r"(a[3]), "r"(b0), "r"(b1));
}

// ---------------------------------------------------------------------------
// Kernel 1: warp-per-row normalize -> bf16; labels; zero accumulators.
// ---------------------------------------------------------------------------
__global__ void __launch_bounds__(256) normalize_kernel(
    const float* __restrict__ feat,
    const int*   __restrict__ lab32)
{
    const int warp = threadIdx.x >> 5;
    const int lane = threadIdx.x & 31;
    const int row  = blockIdx.x * 8 + warp;

    float4 v = *(const float4*)&feat[row * D + lane * 4];
    float ss = v.x * v.x + v.y * v.y + v.z * v.z + v.w * v.w;
    #pragma unroll
    for (int o = 16; o > 0; o >>= 1) ss += __shfl_xor_sync(0xffffffffu, ss, o);
    float inv = 1.0f / fmaxf(sqrtf(ss), 1e-8f);

    float f[4] = { v.x * inv, v.y * inv, v.z * inv, v.w * inv };
    ushort h[4];
    #pragma unroll
    for (int k = 0; k < 4; k++)
        h[k] = __bfloat16_as_ushort(__float2bfloat16_rn(f[k]));
    *(uint2*)&((ushort*)g_f16)[row * D + lane * 4] =
        make_uint2(h[0] | (uint32_t)h[1] << 16, h[2] | (uint32_t)h[3] << 16);

    if (lane == 0) {
        g_pos[row] = 0.0f;
        g_neg[row] = 0.0f;
        bool is64 = true;
        #pragma unroll 8
        for (int i = 0; i < 32; i++)
            if (lab32[2 * i + 1] != 0) { is64 = false; break; }
        g_lab[row] = is64 ? lab32[2 * row] : lab32[row];
    }
}

// ---------------------------------------------------------------------------
// Kernel 2: upper-triangular 128x128 bf16 mma.sync tiles, K=128 single
// product. Fused clip/exp/mask epilogue: row sums + (off-diag) column sums.
// ---------------------------------------------------------------------------
__device__ __forceinline__ void load_chunk(uint32_t stageBase, int chunk,
                                           int aRowBase, int bRowBase, int tid)
{
    const int col = chunk * 32;            // element offset into K
    #pragma unroll
    for (int it = 0; it < 2; it++) {
        int idx = tid + it * 256;
        int r   = idx >> 2;
        int c4  = idx & 3;
        uint32_t s = stageBase + r * ROWPITCH + c4 * 16;
        cpasync16(s,         (const char*)&g_f16[(aRowBase + r) * D + col] + c4 * 16);
        cpasync16(s + TILEB, (const char*)&g_f16[(bRowBase + r) * D + col] + c4 * 16);
    }
}

__global__ void __launch_bounds__(256, 2) sim_mma_kernel()
{
    extern __shared__ char dsm[];
    __shared__ int labA[128];
    __shared__ int labB[128];

    const uint32_t smBase = smem_u32(dsm);
    const int tid  = threadIdx.x;
    const int warp = tid >> 5;
    const int lane = tid & 31;
    const int warpRow = warp >> 1;
    const int warpCol = warp & 1;

    // decode linear tile id -> upper-triangular (i, j), i <= j
    int ti = blockIdx.x;
    int i  = (int)floorf((129.0f - sqrtf(129.0f * 129.0f - 8.0f * (float)ti)) * 0.5f);
    while (i > 0 && ti < i * NT - i * (i - 1) / 2) --i;
    while (ti >= (i + 1) * NT - (i + 1) * i / 2) ++i;
    const int j = i + (ti - (i * NT - i * (i - 1) / 2));
    const bool diag = (i == j);
    const int aRowBase = i * 128;
    const int bRowBase = j * 128;

    if (tid < 128) {
        labA[tid] = g_lab[aRowBase + tid];
        labB[tid] = g_lab[bRowBase + tid];
    }

    #pragma unroll
    for (int s = 0; s < STAGES - 1; s++) {
        load_chunk(smBase + s * STAGEB, s, aRowBase, bRowBase, tid);
        cp_commit();
    }

    float acc[2][8][4];
    #pragma unroll
    for (int a = 0; a < 2; a++)
        #pragma unroll
        for (int b = 0; b < 8; b++)
            #pragma unroll
            for (int k = 0; k < 4; k++) acc[a][b][k] = 0.0f;

    uint32_t aOff[2];
    #pragma unroll
    for (int mi = 0; mi < 2; mi++)
        aOff[mi] = (uint32_t)((warpRow * 32 + mi * 16 + (lane & 15)) * ROWPITCH
                              + ((lane >> 4) * 16));
    uint32_t bOff[4];
    #pragma unroll
    for (int nt = 0; nt < 4; nt++)
        bOff[nt] = (uint32_t)((warpCol * 64 + nt * 16 + (lane & 7) + ((lane & 16) ? 8 : 0))
                              * ROWPITCH + ((lane & 8) ? 16 : 0));

    #pragma unroll 1
    for (int c = 0; c < CHUNKS; c++) {
        cp_wait<STAGES - 2>();
        __syncthreads();

        int nf = c + STAGES - 1;
        if (nf < CHUNKS)
            load_chunk(smBase + (nf % STAGES) * STAGEB, nf, aRowBase, bRowBase, tid);
        cp_commit();

        const uint32_t aS = smBase + (c % STAGES) * STAGEB;
        const uint32_t bS = aS + TILEB;

        #pragma unroll
        for (int k16 = 0; k16 < 2; k16++) {
            uint32_t a[2][4];
            ldmx4(a[0], aS + aOff[0] + k16 * 32);
            ldmx4(a[1], aS + aOff[1] + k16 * 32);
            uint32_t b[4][4];
            #pragma unroll
            for (int nt = 0; nt < 4; nt++)
                ldmx4(b[nt], bS + bOff[nt] + k16 * 32);
            #pragma unroll
            for (int mi = 0; mi < 2; mi++)
                #pragma unroll
                for (int n8 = 0; n8 < 8; n8++) {
                    const uint32_t* bf = b[n8 >> 1];
                    if (n8 & 1) mma16816(acc[mi][n8], a[mi], bf[2], bf[3]);
                    else        mma16816(acc[mi][n8], a[mi], bf[0], bf[1]);
                }
        }
    }

    // ---------------- fused epilogue (row + column sums) ----------------
    const int g   = lane >> 2;
    const int tig = lane & 3;

    float colPos[16], colNeg[16];
    #pragma unroll
    for (int x = 0; x < 16; x++) { colPos[x] = 0.0f; colNeg[x] = 0.0f; }

    #pragma unroll
    for (int mi = 0; mi < 2; mi++) {
        #pragma unroll
        for (int h = 0; h < 2; h++) {
            const int rT   = warpRow * 32 + mi * 16 + h * 8 + g;
            const int lrow = labA[rT];
            float rowPos = 0.0f, rowNeg = 0.0f;
            #pragma unroll
            for (int n8 = 0; n8 < 8; n8++) {
                #pragma unroll
                for (int e = 0; e < 2; e++) {
                    const int cT = warpCol * 64 + n8 * 8 + 2 * tig + e;
                    float v = acc[mi][n8][h * 2 + e];
                    float s = fminf(fmaxf(v * INV_T, -10.0f), 10.0f);
                    float ex = __expf(s);
                    if (diag) ex = (rT == cT) ? 0.0f : ex;
                    bool m = (lrow == labB[cT]);
                    rowNeg += ex;
                    rowPos += m ? ex : 0.0f;
                    if (!diag) {
                        colNeg[n8 * 2 + e] += ex;
                        colPos[n8 * 2 + e] += m ? ex : 0.0f;
                    }
                }
            }
            #pragma unroll
            for (int o = 1; o < 4; o <<= 1) {
                rowPos += __shfl_xor_sync(0xffffffffu, rowPos, o);
                rowNeg += __shfl_xor_sync(0xffffffffu, rowNeg, o);
            }
            if (tig == 0) {
                atomicAdd(&g_pos[aRowBase + rT], rowPos);
                atomicAdd(&g_neg[aRowBase + rT], rowNeg);
            }
        }
    }

    if (!diag) {
        #pragma unroll
        for (int x = 0; x < 16; x++) {
            #pragma unroll
            for (int o = 4; o < 32; o <<= 1) {
                colPos[x] += __shfl_xor_sync(0xffffffffu, colPos[x], o);
                colNeg[x] += __shfl_xor_sync(0xffffffffu, colNeg[x], o);
            }
        }
        if (g == 0) {
            #pragma unroll
            for (int x = 0; x < 16; x++) {
                const int cT = warpCol * 64 + (x >> 1) * 8 + 2 * tig + (x & 1);
                atomicAdd(&g_pos[bRowBase + cT], colPos[x]);
                atomicAdd(&g_neg[bRowBase + cT], colNeg[x]);
            }
        }
    }
}

// ---------------------------------------------------------------------------
// Kernel 3: final loss reduction.
// ---------------------------------------------------------------------------
__global__ void __launch_bounds__(256) loss_kernel(float* __restrict__ out)
{
    int t = threadIdx.x;
    float s = 0.0f;
    for (int idx = t; idx < NROWS; idx += 256) {
        float p = fmaxf(g_pos[idx], 1e-8f);
        float n = fmaxf(g_neg[idx], 1e-8f);
        s += logf(n) - logf(p);
    }
    __shared__ float red[256];
    red[t] = s;
    __syncthreads();
    #pragma unroll
    for (int o = 128; o > 0; o >>= 1) {
        if (t < o) red[t] += red[t + o];
        __syncthreads();
    }
    if (t == 0) out[0] = red[0] * (1.0f / (float)NROWS);
}

// ---------------------------------------------------------------------------
extern "C" void kernel_launch(void* const* d_in, const int* in_sizes, int n_in,
                              void* d_out, int out_size)
{
    const float* feat  = (const float*)d_in[0];
    const int*   lab32 = (const int*)d_in[1];
    float*       out   = (float*)d_out;

    static bool attr_set = false;
    if (!attr_set) {
        cudaFuncSetAttribute(sim_mma_kernel, cudaFuncAttributeMaxDynamicSharedMemorySize,
                             SMEM_DYN_BYTES);
        attr_set = true;
    }

    normalize_kernel<<<NROWS / 8, 256>>>(feat, lab32);
    sim_mma_kernel<<<NTILES, 256, SMEM_DYN_BYTES>>>();
    loss_kernel<<<1, 256>>>(out);
}

// round 8
// speedup vs baseline: 4.2383x; 1.1343x over previous
#include <cuda_runtime.h>
#include <cuda_bf16.h>
#include <cstdint>
#include <math.h>

#define NROWS 8192
#define D     128
#define INV_T (1.0f / 0.07f)
#define SCALE_LOG2 (INV_T * 1.44269504089f)
#define CLIP_LOG2  (10.0f * 1.44269504089f)

#define NT       64
#define NTILES   2080          // NT*(NT+1)/2
#define GRID     296           // 2 persistent CTAs per SM
#define STAGES   4
#define CHUNKS   4             // single bf16 product, 4 x k32 chunks
#define ROWPITCH 80            // 64B data + 16B pad (LDSM conflict-free)
#define TILEB    (128 * ROWPITCH)          // 10240
#define STAGEB   (2 * TILEB)               // 20480
#define SMEM_DYN_BYTES (STAGES * STAGEB)   // 81920

// ---------------- device scratch -------------------------------------------
__device__ __nv_bfloat16 g_f16[NROWS * D];
__device__ float g_pos[NROWS];
__device__ float g_neg[NROWS];
__device__ int   g_lab[NROWS];

// ---------------- helpers ---------------------------------------------------
__device__ __forceinline__ uint32_t smem_u32(const void* p) {
    return (uint32_t)__cvta_generic_to_shared(p);
}
__device__ __forceinline__ void cpasync16(uint32_t s, const void* g) {
    asm volatile("cp.async.cg.shared.global [%0], [%1], 16;" :: "r"(s), "l"(g));
}
__device__ __forceinline__ void cp_commit() {
    asm volatile("cp.async.commit_group;" ::: "memory");
}
template <int N>
__device__ __forceinline__ void cp_wait() {
    asm volatile("cp.async.wait_group %0;" :: "n"(N) : "memory");
}
__device__ __forceinline__ void ldmx4(uint32_t* r, uint32_t addr) {
    asm volatile("ldmatrix.sync.aligned.m8n8.x4.shared.b16 {%0,%1,%2,%3}, [%4];"
                 : "=r"(r[0]), "=r"(r[1]), "=r"(r[2]), "=r"(r[3]) : "r"(addr));
}
__device__ __forceinline__ void mma16816(float* c, const uint32_t* a, uint32_t b0, uint32_t b1) {
    asm volatile(
        "mma.sync.aligned.m16n8k16.row.col.f32.bf16.bf16.f32 "
        "{%0,%1,%2,%3}, {%4,%5,%6,%7}, {%8,%9}, {%0,%1,%2,%3};"
        : "+f"(c[0]), "+f"(c[1]), "+f"(c[2]), "+f"(c[3])
        : "r"(a[0]), "r"(a[1]), "r"(a[2]), "r"(a[3]), "r"(b0), "r"(b1));
}
__device__ __forceinline__ float ex2(float x) {
    float r;
    asm("ex2.approx.f32 %0, %1;" : "=f"(r) : "f"(x));
    return r;
}
// decode linear tile id -> upper-triangular (i, j), i <= j
__device__ __forceinline__ void decode_tile(int ti, int& i, int& j) {
    i = (int)floorf((129.0f - sqrtf(129.0f * 129.0f - 8.0f * (float)ti)) * 0.5f);
    while (i > 0 && ti < i * NT - i * (i - 1) / 2) --i;
    while (ti >= (i + 1) * NT - (i + 1) * i / 2) ++i;
    j = i + (ti - (i * NT - i * (i - 1) / 2));
}

// ---------------------------------------------------------------------------
// Kernel 1: warp-per-row normalize -> bf16; labels; zero accumulators.
// ---------------------------------------------------------------------------
__global__ void __launch_bounds__(256) normalize_kernel(
    const float* __restrict__ feat,
    const int*   __restrict__ lab32)
{
    const int warp = threadIdx.x >> 5;
    const int lane = threadIdx.x & 31;
    const int row  = blockIdx.x * 8 + warp;

    float4 v = *(const float4*)&feat[row * D + lane * 4];
    float ss = v.x * v.x + v.y * v.y + v.z * v.z + v.w * v.w;
    #pragma unroll
    for (int o = 16; o > 0; o >>= 1) ss += __shfl_xor_sync(0xffffffffu, ss, o);
    float inv = 1.0f / fmaxf(sqrtf(ss), 1e-8f);

    float f[4] = { v.x * inv, v.y * inv, v.z * inv, v.w * inv };
    ushort h[4];
    #pragma unroll
    for (int k = 0; k < 4; k++)
        h[k] = __bfloat16_as_ushort(__float2bfloat16_rn(f[k]));
    *(uint2*)&((ushort*)g_f16)[row * D + lane * 4] =
        make_uint2(h[0] | (uint32_t)h[1] << 16, h[2] | (uint32_t)h[3] << 16);

    if (lane == 0) {
        g_pos[row] = 0.0f;
        g_neg[row] = 0.0f;
        bool is64 = true;
        #pragma unroll 8
        for (int i = 0; i < 32; i++)
            if (lab32[2 * i + 1] != 0) { is64 = false; break; }
        g_lab[row] = is64 ? lab32[2 * row] : lab32[row];
    }
}

// ---------------------------------------------------------------------------
// Kernel 2: persistent upper-triangular bf16 mma.sync tiles; cp.async ring
// continues across tile boundaries so epilogue overlaps next tile's loads.
// ---------------------------------------------------------------------------
__device__ __forceinline__ void load_chunk(uint32_t stageBase, int chunk,
                                           int aRowBase, int bRowBase, int tid)
{
    const int col = chunk * 32;
    #pragma unroll
    for (int it = 0; it < 2; it++) {
        int idx = tid + it * 256;
        int r   = idx >> 2;
        int c4  = idx & 3;
        uint32_t s = stageBase + r * ROWPITCH + c4 * 16;
        cpasync16(s,         (const char*)&g_f16[(aRowBase + r) * D + col] + c4 * 16);
        cpasync16(s + TILEB, (const char*)&g_f16[(bRowBase + r) * D + col] + c4 * 16);
    }
}

__global__ void __launch_bounds__(256, 2) sim_mma_kernel()
{
    extern __shared__ char dsm[];
    __shared__ int labA[2][128];
    __shared__ int labB[2][128];

    const uint32_t smBase = smem_u32(dsm);
    const int tid  = threadIdx.x;
    const int warp = tid >> 5;
    const int lane = tid & 31;
    const int warpRow = warp >> 1;
    const int warpCol = warp & 1;
    const int g   = lane >> 2;
    const int tig = lane & 3;

    uint32_t aOff[2];
    #pragma unroll
    for (int mi = 0; mi < 2; mi++)
        aOff[mi] = (uint32_t)((warpRow * 32 + mi * 16 + (lane & 15)) * ROWPITCH
                              + ((lane >> 4) * 16));
    uint32_t bOff[4];
    #pragma unroll
    for (int nt = 0; nt < 4; nt++)
        bOff[nt] = (uint32_t)((warpCol * 64 + nt * 16 + (lane & 7) + ((lane & 16) ? 8 : 0))
                              * ROWPITCH + ((lane & 8) ? 16 : 0));

    int ti = blockIdx.x;
    if (ti >= NTILES) return;
    int i, j;
    decode_tile(ti, i, j);
    int aR = i * 128, bR = j * 128;

    // prologue: chunks 0..2 of first tile
    #pragma unroll
    for (int s = 0; s < 3; s++) {
        load_chunk(smBase + s * STAGEB, s, aR, bR, tid);
        cp_commit();
    }

    int tlocal = 0;
    #pragma unroll 1
    while (true) {
        const bool diag = (aR == bR);
        const int ti_next = ti + GRID;
        const bool hasNext = (ti_next < NTILES);
        int aRn = 0, bRn = 0;
        if (hasNext) {
            int in, jn;
            decode_tile(ti_next, in, jn);
            aRn = in * 128; bRn = jn * 128;
        }

        float acc[2][8][4];
        #pragma unroll
        for (int a = 0; a < 2; a++)
            #pragma unroll
            for (int b = 0; b < 8; b++)
                #pragma unroll
                for (int k = 0; k < 4; k++) acc[a][b][k] = 0.0f;

        const int lb = tlocal & 1;

        #pragma unroll
        for (int c = 0; c < CHUNKS; c++) {
            cp_wait<2>();
            __syncthreads();

            if (c == 0 && tid < 128) {
                labA[lb][tid] = g_lab[aR + tid];
                labB[lb][tid] = g_lab[bR + tid];
            }

            // keep the ring rolling: c==0 -> this tile chunk 3; c>=1 -> next tile c-1
            if (c == 0)
                load_chunk(smBase + 3 * STAGEB, 3, aR, bR, tid);
            else if (hasNext)
                load_chunk(smBase + (c - 1) * STAGEB, c - 1, aRn, bRn, tid);
            cp_commit();

            const uint32_t aS = smBase + c * STAGEB;
            const uint32_t bS = aS + TILEB;

            #pragma unroll
            for (int k16 = 0; k16 < 2; k16++) {
                uint32_t a[2][4];
                ldmx4(a[0], aS + aOff[0] + k16 * 32);
                ldmx4(a[1], aS + aOff[1] + k16 * 32);
                uint32_t b[4][4];
                #pragma unroll
                for (int nt = 0; nt < 4; nt++)
                    ldmx4(b[nt], bS + bOff[nt] + k16 * 32);
                #pragma unroll
                for (int mi = 0; mi < 2; mi++)
                    #pragma unroll
                    for (int n8 = 0; n8 < 8; n8++) {
                        const uint32_t* bf = b[n8 >> 1];
                        if (n8 & 1) mma16816(acc[mi][n8], a[mi], bf[2], bf[3]);
                        else        mma16816(acc[mi][n8], a[mi], bf[0], bf[1]);
                    }
            }
        }

        // ---------------- fused epilogue (row + column sums) ----------------
        float colPos[16], colNeg[16];
        #pragma unroll
        for (int x = 0; x < 16; x++) { colPos[x] = 0.0f; colNeg[x] = 0.0f; }

        #pragma unroll
        for (int mi = 0; mi < 2; mi++) {
            #pragma unroll
            for (int h = 0; h < 2; h++) {
                const int rT   = warpRow * 32 + mi * 16 + h * 8 + g;
                const int lrow = labA[lb][rT];
                float rowPos = 0.0f, rowNeg = 0.0f;
                #pragma unroll
                for (int n8 = 0; n8 < 8; n8++) {
                    #pragma unroll
                    for (int e = 0; e < 2; e++) {
                        const int cT = warpCol * 64 + n8 * 8 + 2 * tig + e;
                        float v = acc[mi][n8][h * 2 + e];
                        float s = fminf(fmaxf(v * SCALE_LOG2, -CLIP_LOG2), CLIP_LOG2);
                        float exv = ex2(s);
                        if (diag) exv = (rT == cT) ? 0.0f : exv;
                        bool m = (lrow == labB[lb][cT]);
                        rowNeg += exv;
                        rowPos += m ? exv : 0.0f;
                        if (!diag) {
                            colNeg[n8 * 2 + e] += exv;
                            colPos[n8 * 2 + e] += m ? exv : 0.0f;
                        }
                    }
                }
                #pragma unroll
                for (int o = 1; o < 4; o <<= 1) {
                    rowPos += __shfl_xor_sync(0xffffffffu, rowPos, o);
                    rowNeg += __shfl_xor_sync(0xffffffffu, rowNeg, o);
                }
                if (tig == 0) {
                    atomicAdd(&g_pos[aR + rT], rowPos);
                    atomicAdd(&g_neg[aR + rT], rowNeg);
                }
            }
        }

        if (!diag) {
            #pragma unroll
            for (int x = 0; x < 16; x++) {
                #pragma unroll
                for (int o = 4; o < 32; o <<= 1) {
                    colPos[x] += __shfl_xor_sync(0xffffffffu, colPos[x], o);
                    colNeg[x] += __shfl_xor_sync(0xffffffffu, colNeg[x], o);
                }
            }
            if (g == 0) {
                #pragma unroll
                for (int x = 0; x < 16; x++) {
                    const int cT = warpCol * 64 + (x >> 1) * 8 + 2 * tig + (x & 1);
                    atomicAdd(&g_pos[bR + cT], colPos[x]);
                    atomicAdd(&g_neg[bR + cT], colNeg[x]);
                }
            }
        }

        if (!hasNext) break;
        ti = ti_next; aR = aRn; bR = bRn; ++tlocal;
    }
}

// ---------------------------------------------------------------------------
// Kernel 3: final loss reduction (single block, 1024 threads).
// ---------------------------------------------------------------------------
__global__ void __launch_bounds__(1024) loss_kernel(float* __restrict__ out)
{
    int t = threadIdx.x;
    float s = 0.0f;
    for (int idx = t; idx < NROWS; idx += 1024) {
        float p = fmaxf(g_pos[idx], 1e-8f);
        float n = fmaxf(g_neg[idx], 1e-8f);
        s += logf(n) - logf(p);
    }
    __shared__ float red[1024];
    red[t] = s;
    __syncthreads();
    #pragma unroll
    for (int o = 512; o > 0; o >>= 1) {
        if (t < o) red[t] += red[t + o];
        __syncthreads();
    }
    if (t == 0) out[0] = red[0] * (1.0f / (float)NROWS);
}

// ---------------------------------------------------------------------------
extern "C" void kernel_launch(void* const* d_in, const int* in_sizes, int n_in,
                              void* d_out, int out_size)
{
    const float* feat  = (const float*)d_in[0];
    const int*   lab32 = (const int*)d_in[1];
    float*       out   = (float*)d_out;

    static bool attr_set = false;
    if (!attr_set) {
        cudaFuncSetAttribute(sim_mma_kernel, cudaFuncAttributeMaxDynamicSharedMemorySize,
                             SMEM_DYN_BYTES);
        attr_set = true;
    }

    normalize_kernel<<<NROWS / 8, 256>>>(feat, lab32);
    sim_mma_kernel<<<GRID, 256, SMEM_DYN_BYTES>>>();
    loss_kernel<<<1, 1024>>>(out);
}